// round 2
// baseline (speedup 1.0000x reference)
#include <cuda_runtime.h>
#include <math.h>

#define BB 2
#define HH 192
#define WW 192
#define HQ 384
#define EPSF 1e-7f

typedef unsigned long long ull;

// ---- packed fp32x2 helpers (sm_103a FFMA2 — only reachable via PTX) ----
__device__ __forceinline__ ull pk2(float v) {
    ull r; asm("mov.b64 %0, {%1, %1};" : "=l"(r) : "f"(v)); return r;
}
__device__ __forceinline__ void ffma2(ull& d, ull a, ull b) {
    asm("fma.rn.f32x2 %0, %1, %2, %0;" : "+l"(d) : "l"(a), "l"(b));
}
__device__ __forceinline__ void unpk2(float& lo, float& hi, ull v) {
    asm("mov.b64 {%0, %1}, %2;" : "=f"(lo), "=f"(hi) : "l"(v));
}

// ---------------- scratch (device globals: allocation-free) ----------------
__device__ float g_a4 [BB*96*96*32];
__device__ float g_a32[BB*24*24*32];
__device__ float g_X  [BB*HH*WW*96];   // concat input to conv3x3
__device__ float g_aspp[BB*HH*WW*96];  // conv3x3 output

// ---------------- conv1x1 + ReLU (Cout = 32) ----------------
__global__ void conv1x1_relu_k(const float* __restrict__ in,
                               const float* __restrict__ w,
                               const float* __restrict__ bias,
                               float* __restrict__ out,
                               int npix, int Cin, int ostride, int coff) {
    __shared__ float sw[160*32];
    __shared__ float sb[32];
    int tid = threadIdx.x;
    for (int i = tid; i < Cin*32; i += blockDim.x) sw[i] = w[i];
    if (tid < 32) sb[tid] = bias[tid];
    __syncthreads();
    int px = blockIdx.x * 32 + (tid >> 3);   // 8 threads per pixel
    int co = (tid & 7) * 4;                  // 4 consecutive out-channels
    if (px >= npix) return;
    const float* ip = in + (long)px * Cin;
    ull a01 = 0, a23 = 0;
    for (int ci = 0; ci < Cin; ci++) {
        ull xv = pk2(ip[ci]);
        const ull* wv = (const ull*)&sw[ci*32 + co];
        ffma2(a01, xv, wv[0]);
        ffma2(a23, xv, wv[1]);
    }
    float v0, v1, v2, v3;
    unpk2(v0, v1, a01);
    unpk2(v2, v3, a23);
    float* op = out + (long)px * ostride + coff + co;
    op[0] = fmaxf(v0 + sb[co+0], 0.f);
    op[1] = fmaxf(v1 + sb[co+1], 0.f);
    op[2] = fmaxf(v2 + sb[co+2], 0.f);
    op[3] = fmaxf(v3 + sb[co+3], 0.f);
}

// ---------------- bilinear upsample a4(96x96) & a32(24x24) -> X[.., 32..95] ----------------
__global__ void upsample_k() {
    int idx = blockIdx.x * blockDim.x + threadIdx.x;
    const int total = BB*HH*WW*64;
    if (idx >= total) return;
    int ch2 = idx & 63;
    int p = idx >> 6;
    int x = p % WW;
    int y = (p / WW) % HH;
    int b = p / (WW*HH);

    int S, ch;
    const float* src;
    if (ch2 < 32) { S = 96; ch = ch2;       src = g_a4;  }
    else          { S = 24; ch = ch2 - 32;  src = g_a32; }
    float scale = (float)S / (float)HH;   // 0.5 or 0.125 (exact)
    float fy = (y + 0.5f) * scale - 0.5f;
    float fx = (x + 0.5f) * scale - 0.5f;
    int y0 = (int)floorf(fy); float ty = fy - (float)y0;
    int x0 = (int)floorf(fx); float tx = fx - (float)x0;
    int y0c = max(y0, 0), y1c = min(y0 + 1, S - 1);
    int x0c = max(x0, 0), x1c = min(x0 + 1, S - 1);
    const float* base = src + (long)b * S * S * 32;
    float v00 = base[(y0c*S + x0c)*32 + ch];
    float v01 = base[(y0c*S + x1c)*32 + ch];
    float v10 = base[(y1c*S + x0c)*32 + ch];
    float v11 = base[(y1c*S + x1c)*32 + ch];
    float v = (1.f-ty)*((1.f-tx)*v00 + tx*v01) + ty*((1.f-tx)*v10 + tx*v11);
    g_X[((long)(b*HH + y)*WW + x)*96 + 32 + ch2] = v;
}

// ---------------- conv3x3 (96 -> 96) + ReLU ----------------
// block: 16x16 pixel tile, 384 threads. thread = 8 px x 8 co micro-tile.
// FFMA2 inner loop: acc2[i][p] over col-pairs; x broadcast packed once per (ky,ci).
__global__ void __launch_bounds__(384, 1)
conv3x3_k(const float* __restrict__ wf, const float* __restrict__ bf) {
    extern __shared__ float cs[];
    float* tile = cs;                 // 16*18*18 = 5184 floats
    float* ws   = cs + 16*18*18;      // 9*16*96 = 13824 floats

    int t   = threadIdx.x;
    int bx  = blockIdx.x, by = blockIdx.y, b = blockIdx.z;
    int cog = t >> 5;                 // 0..11 -> co group of 8
    int pxg = t & 31;
    int row = pxg >> 1;               // 0..15
    int xh  = pxg & 1;                // half-row: pixels xh*8..xh*8+7

    ull acc2[8][4];
    #pragma unroll
    for (int i = 0; i < 8; i++)
        #pragma unroll
        for (int j = 0; j < 4; j++) acc2[i][j] = 0ULL;

    #pragma unroll 1
    for (int c0 = 0; c0 < 96; c0 += 16) {
        __syncthreads();
        // load input tile chunk (zero pad)
        for (int idx = t; idx < 18*18*16; idx += 384) {
            int ci = idx & 15;
            int p  = idx >> 4;
            int xx = p % 18, yy = p / 18;
            int gy = by*16 + yy - 1, gx = bx*16 + xx - 1;
            float v = 0.f;
            if (gy >= 0 && gy < HH && gx >= 0 && gx < WW)
                v = g_X[((long)(b*HH + gy)*WW + gx)*96 + c0 + ci];
            tile[(ci*18 + yy)*18 + xx] = v;
        }
        // load weight chunk: ws[k][ci][co] = wf[k][c0+ci][co] (contiguous per k)
        for (int idx = t; idx < 9*16*96; idx += 384) {
            int k = idx / (16*96);
            int r = idx - k*(16*96);
            ws[k*16*96 + r] = wf[(k*96 + c0)*96 + r];
        }
        __syncthreads();

        #pragma unroll 1
        for (int ky = 0; ky < 3; ky++) {
            #pragma unroll 1
            for (int ci = 0; ci < 16; ci++) {
                const float* tr = &tile[(ci*18 + row + ky)*18 + xh*8];
                ull xd[10];
                #pragma unroll
                for (int q = 0; q < 10; q++) xd[q] = pk2(tr[q]);
                #pragma unroll
                for (int kx = 0; kx < 3; kx++) {
                    const ull* wp = (const ull*)&ws[((ky*3 + kx)*16 + ci)*96 + cog*8];
                    ull w0 = wp[0], w1 = wp[1], w2 = wp[2], w3 = wp[3];
                    #pragma unroll
                    for (int i = 0; i < 8; i++) {
                        ull x = xd[i + kx];
                        ffma2(acc2[i][0], x, w0);
                        ffma2(acc2[i][1], x, w1);
                        ffma2(acc2[i][2], x, w2);
                        ffma2(acc2[i][3], x, w3);
                    }
                }
            }
        }
    }
    // epilogue: bias + relu
    float bv[8];
    #pragma unroll
    for (int j = 0; j < 8; j++) bv[j] = bf[cog*8 + j];
    int gy = by*16 + row;
    #pragma unroll
    for (int i = 0; i < 8; i++) {
        int gx = bx*16 + xh*8 + i;
        float* op = &g_aspp[((long)(b*HH + gy)*WW + gx)*96 + cog*8];
        #pragma unroll
        for (int j = 0; j < 4; j++) {
            float lo, hi;
            unpk2(lo, hi, acc2[i][j]);
            op[2*j]   = fmaxf(lo + bv[2*j],   0.f);
            op[2*j+1] = fmaxf(hi + bv[2*j+1], 0.f);
        }
    }
}

// ---------------- query kernel: gather + MLP(102->64->64->1) + blend ----------------
// persistent blocks; per tile: 32 queries x 4 corners = 128 rows.
#define QS_W0 0
#define QS_B0 6528
#define QS_W1 6592
#define QS_B1 10688
#define QS_W2 10752
#define QS_A  10816
#define QS_AREA (10816 + 13312)
#define QS_PRED (QS_AREA + 128)
#define QS_PART (QS_PRED + 128)
#define QS_OFF  (QS_PART + 256)
#define QS_TOTAL (QS_OFF + 128)       // 24768 floats = 99072 bytes

__global__ void __launch_bounds__(256, 2)
query_k(const float* __restrict__ coords, const float* __restrict__ cells,
        const float* __restrict__ mw0, const float* __restrict__ mb0,
        const float* __restrict__ mw1, const float* __restrict__ mb1,
        const float* __restrict__ mw2, const float* __restrict__ mb2,
        float* __restrict__ out) {
    extern __shared__ float qs[];
    float* sW0 = qs + QS_W0;
    float* sB0 = qs + QS_B0;
    float* sW1 = qs + QS_W1;
    float* sB1 = qs + QS_B1;
    float* sW2 = qs + QS_W2;
    float* sA  = qs + QS_A;
    float* sArea = qs + QS_AREA;
    float* sPred = qs + QS_PRED;
    float* sPart = qs + QS_PART;
    int*   sOff  = (int*)(qs + QS_OFF);
    __shared__ float sB2;

    int t = threadIdx.x;
    for (int i = t; i < 6528; i += 256) sW0[i] = mw0[i];
    for (int i = t; i < 4096; i += 256) sW1[i] = mw1[i];
    if (t < 64) { sB0[t] = mb0[t]; sB1[t] = mb1[t]; sW2[t] = mw2[t]; }
    if (t == 0) sB2 = mb2[0];
    __syncthreads();

    const int NT = (BB*HQ*HQ) / 32;   // 9216 tiles
    int rg = t >> 4;   // row group: rows rg*8 .. rg*8+7
    int cg = t & 15;   // col group: cols cg*4 .. cg*4+3

    for (int tileI = blockIdx.x; tileI < NT; tileI += gridDim.x) {
        // ---- Phase A: per-row meta ----
        if (t < 128) {
            int row = t;
            int q = tileI*32 + (row >> 2);
            int corner = row & 3;
            int b = q / (HQ*HQ);
            float cy = coords[q*2 + 0], cx = coords[q*2 + 1];
            float cly = cells[q*2 + 0], clx = cells[q*2 + 1];
            float vy = (corner & 2) ? 1.f : -1.f;
            float vx = (corner & 1) ? 1.f : -1.f;
            float yc = cy + vy * (1.f/(float)HH) + EPSF;
            float xc = cx + vx * (1.f/(float)WW) + EPSF;
            yc = fminf(fmaxf(yc, -1.f + EPSF), 1.f - EPSF);
            xc = fminf(fmaxf(xc, -1.f + EPSF), 1.f - EPSF);
            int iy = (int)rintf((yc + 1.f) * ((float)HH * 0.5f) - 0.5f);
            int ix = (int)rintf((xc + 1.f) * ((float)WW * 0.5f) - 0.5f);
            iy = min(max(iy, 0), HH - 1);
            ix = min(max(ix, 0), WW - 1);
            float sy = (((float)iy + 0.5f) / (float)HH) * 2.f - 1.f;
            float sx = (((float)ix + 0.5f) / (float)WW) * 2.f - 1.f;
            float ry = (cy - sy) * (float)HH;
            float rx = (cx - sx) * (float)WW;
            sA[row*104 +  96] = ry;
            sA[row*104 +  97] = rx;
            sA[row*104 +  98] = cy;
            sA[row*104 +  99] = cx;
            sA[row*104 + 100] = cly * (float)HH;
            sA[row*104 + 101] = clx * (float)WW;
            sArea[row] = fabsf(ry * rx) + EPSF;
            sOff[row] = ((b*HH + iy)*WW + ix) * 96;
        }
        __syncthreads();
        // ---- Phase B: gather features (96 floats per row) ----
        {
            int row = t >> 1, half = t & 1;
            const float4* src = (const float4*)(g_aspp + sOff[row] + half*48);
            float4* dst = (float4*)&sA[row*104 + half*48];
            #pragma unroll
            for (int i = 0; i < 12; i++) dst[i] = src[i];
        }
        __syncthreads();

        // ---- GEMM1: [128x102] @ [102x64] (FFMA2) ----
        ull acc2[8][2];
        #pragma unroll
        for (int i = 0; i < 8; i++) { acc2[i][0] = 0ULL; acc2[i][1] = 0ULL; }
        #pragma unroll 1
        for (int k2 = 0; k2 < 51; k2++) {
            int k = k2*2;
            const ull* b0p = (const ull*)&sW0[k*64 + cg*4];
            const ull* b1p = (const ull*)&sW0[(k+1)*64 + cg*4];
            ull b00 = b0p[0], b01 = b0p[1];
            ull b10 = b1p[0], b11 = b1p[1];
            #pragma unroll
            for (int i = 0; i < 8; i++) {
                float2 a = *(const float2*)&sA[(rg*8 + i)*104 + k];
                ull ax = pk2(a.x), ay = pk2(a.y);
                ffma2(acc2[i][0], ax, b00);
                ffma2(acc2[i][1], ax, b01);
                ffma2(acc2[i][0], ay, b10);
                ffma2(acc2[i][1], ay, b11);
            }
        }
        __syncthreads();
        #pragma unroll
        for (int i = 0; i < 8; i++) {
            #pragma unroll
            for (int j = 0; j < 2; j++) {
                float lo, hi;
                unpk2(lo, hi, acc2[i][j]);
                sA[(rg*8 + i)*104 + cg*4 + 2*j]     = fmaxf(lo + sB0[cg*4 + 2*j],     0.f);
                sA[(rg*8 + i)*104 + cg*4 + 2*j + 1] = fmaxf(hi + sB0[cg*4 + 2*j + 1], 0.f);
            }
        }
        __syncthreads();

        // ---- GEMM2: [128x64] @ [64x64] (FFMA2) ----
        #pragma unroll
        for (int i = 0; i < 8; i++) { acc2[i][0] = 0ULL; acc2[i][1] = 0ULL; }
        #pragma unroll 1
        for (int k2 = 0; k2 < 32; k2++) {
            int k = k2*2;
            const ull* b0p = (const ull*)&sW1[k*64 + cg*4];
            const ull* b1p = (const ull*)&sW1[(k+1)*64 + cg*4];
            ull b00 = b0p[0], b01 = b0p[1];
            ull b10 = b1p[0], b11 = b1p[1];
            #pragma unroll
            for (int i = 0; i < 8; i++) {
                float2 a = *(const float2*)&sA[(rg*8 + i)*104 + k];
                ull ax = pk2(a.x), ay = pk2(a.y);
                ffma2(acc2[i][0], ax, b00);
                ffma2(acc2[i][1], ax, b01);
                ffma2(acc2[i][0], ay, b10);
                ffma2(acc2[i][1], ay, b11);
            }
        }
        __syncthreads();
        #pragma unroll
        for (int i = 0; i < 8; i++) {
            #pragma unroll
            for (int j = 0; j < 2; j++) {
                float lo, hi;
                unpk2(lo, hi, acc2[i][j]);
                sA[(rg*8 + i)*104 + cg*4 + 2*j]     = fmaxf(lo + sB1[cg*4 + 2*j],     0.f);
                sA[(rg*8 + i)*104 + cg*4 + 2*j + 1] = fmaxf(hi + sB1[cg*4 + 2*j + 1], 0.f);
            }
        }
        __syncthreads();

        // ---- GEMM3: [128x64] @ [64x1] (FFMA2) ----
        {
            int row = t >> 1, half = t & 1;
            const ull* ap = (const ull*)&sA[row*104 + half*32];
            const ull* wp = (const ull*)&sW2[half*32];
            ull s2 = 0ULL;
            #pragma unroll
            for (int c = 0; c < 16; c++) ffma2(s2, ap[c], wp[c]);
            float lo, hi;
            unpk2(lo, hi, s2);
            sPart[t] = lo + hi;
        }
        __syncthreads();
        if (t < 128) sPred[t] = sPart[2*t] + sPart[2*t + 1] + sB2;
        __syncthreads();
        // ---- blend corners (pred c pairs with area of corner 3-c) ----
        if (t < 32) {
            int q = tileI*32 + t;
            float num = 0.f, den = 0.f;
            #pragma unroll
            for (int c = 0; c < 4; c++) {
                float ar = sArea[t*4 + (3 - c)];
                num = fmaf(sPred[t*4 + c], ar, num);
                den += ar;
            }
            out[q] = num / den;
        }
        __syncthreads();
    }
}

// ---------------- launch ----------------
extern "C" void kernel_launch(void* const* d_in, const int* in_sizes, int n_in,
                              void* d_out, int out_size) {
    const float* feats2  = (const float*)d_in[0];
    const float* feats4  = (const float*)d_in[1];
    const float* feats32 = (const float*)d_in[2];
    const float* coords  = (const float*)d_in[3];
    const float* cells   = (const float*)d_in[4];
    const float* w2  = (const float*)d_in[5];
    const float* b2  = (const float*)d_in[6];
    const float* w4  = (const float*)d_in[7];
    const float* b4  = (const float*)d_in[8];
    const float* w32 = (const float*)d_in[9];
    const float* b32 = (const float*)d_in[10];
    const float* wf  = (const float*)d_in[11];
    const float* bf  = (const float*)d_in[12];
    const float* mw0 = (const float*)d_in[13];
    const float* mb0 = (const float*)d_in[14];
    const float* mw1 = (const float*)d_in[15];
    const float* mb1 = (const float*)d_in[16];
    const float* mw2 = (const float*)d_in[17];
    const float* mb2 = (const float*)d_in[18];
    float* out = (float*)d_out;

    float *pX, *pA4, *pA32;
    cudaGetSymbolAddress((void**)&pX,  g_X);
    cudaGetSymbolAddress((void**)&pA4, g_a4);
    cudaGetSymbolAddress((void**)&pA32, g_a32);

    cudaFuncSetAttribute(conv3x3_k, cudaFuncAttributeMaxDynamicSharedMemorySize, (16*18*18 + 9*16*96) * 4);
    cudaFuncSetAttribute(query_k,  cudaFuncAttributeMaxDynamicSharedMemorySize, QS_TOTAL * 4);

    // conv1x1 heads
    {
        int npix = BB*HH*WW;   // 73728
        conv1x1_relu_k<<<(npix + 31)/32, 256>>>(feats2, w2, b2, pX, npix, 64, 96, 0);
    }
    {
        int npix = BB*96*96;   // 18432
        conv1x1_relu_k<<<(npix + 31)/32, 256>>>(feats4, w4, b4, pA4, npix, 96, 32, 0);
    }
    {
        int npix = BB*24*24;   // 1152
        conv1x1_relu_k<<<(npix + 31)/32, 256>>>(feats32, w32, b32, pA32, npix, 160, 32, 0);
    }
    // upsample + concat
    {
        int total = BB*HH*WW*64;
        upsample_k<<<(total + 255)/256, 256>>>();
    }
    // conv3x3 fuse
    {
        dim3 grid(WW/16, HH/16, BB);
        conv3x3_k<<<grid, 384, (16*18*18 + 9*16*96) * 4>>>(wf, bf);
    }
    // query MLP (persistent)
    {
        query_k<<<296, 256, QS_TOTAL * 4>>>(coords, cells, mw0, mb0, mw1, mb1, mw2, mb2, out);
    }
}

// round 3
// speedup vs baseline: 2.0186x; 2.0186x over previous
#include <cuda_runtime.h>
#include <math.h>

#define BB 2
#define HH 192
#define WW 192
#define HQ 384
#define EPSF 1e-7f

// ---- tf32 mma helpers ----
__device__ __forceinline__ unsigned cvt_tf32(float f) {
    unsigned r; asm("cvt.rna.tf32.f32 %0, %1;" : "=r"(r) : "f"(f)); return r;
}
__device__ __forceinline__ void mma_tf32(float& c0, float& c1, float& c2, float& c3,
                                         unsigned a0, unsigned a1, unsigned a2, unsigned a3,
                                         unsigned b0, unsigned b1) {
    asm("mma.sync.aligned.m16n8k8.row.col.f32.tf32.tf32.f32 "
        "{%0,%1,%2,%3},{%4,%5,%6,%7},{%8,%9},{%0,%1,%2,%3};"
        : "+f"(c0), "+f"(c1), "+f"(c2), "+f"(c3)
        : "r"(a0), "r"(a1), "r"(a2), "r"(a3), "r"(b0), "r"(b1));
}

// ---------------- scratch ----------------
__device__ float g_a4 [BB*96*96*32];
__device__ float g_a32[BB*24*24*32];
__device__ float g_X  [BB*HH*WW*96];
__device__ float g_aspp[BB*HH*WW*96];

// ---------------- conv1x1 + ReLU (Cout = 32), exact fp32 ----------------
__global__ void conv1x1_relu_k(const float* __restrict__ in,
                               const float* __restrict__ w,
                               const float* __restrict__ bias,
                               float* __restrict__ out,
                               int npix, int Cin, int ostride, int coff) {
    __shared__ float sw[160*32];
    __shared__ float sb[32];
    int tid = threadIdx.x;
    for (int i = tid; i < Cin*32; i += blockDim.x) sw[i] = w[i];
    if (tid < 32) sb[tid] = bias[tid];
    __syncthreads();
    int px = blockIdx.x * 32 + (tid >> 3);
    int co = (tid & 7) * 4;
    if (px >= npix) return;
    const float* ip = in + (long)px * Cin;
    float a0 = 0.f, a1 = 0.f, a2 = 0.f, a3 = 0.f;
    for (int ci = 0; ci < Cin; ci++) {
        float xv = ip[ci];
        float4 wv = *(const float4*)&sw[ci*32 + co];
        a0 = fmaf(xv, wv.x, a0);
        a1 = fmaf(xv, wv.y, a1);
        a2 = fmaf(xv, wv.z, a2);
        a3 = fmaf(xv, wv.w, a3);
    }
    float* op = out + (long)px * ostride + coff + co;
    op[0] = fmaxf(a0 + sb[co+0], 0.f);
    op[1] = fmaxf(a1 + sb[co+1], 0.f);
    op[2] = fmaxf(a2 + sb[co+2], 0.f);
    op[3] = fmaxf(a3 + sb[co+3], 0.f);
}

// ---------------- bilinear upsample ----------------
__global__ void upsample_k() {
    int idx = blockIdx.x * blockDim.x + threadIdx.x;
    const int total = BB*HH*WW*64;
    if (idx >= total) return;
    int ch2 = idx & 63;
    int p = idx >> 6;
    int x = p % WW;
    int y = (p / WW) % HH;
    int b = p / (WW*HH);
    int S, ch;
    const float* src;
    if (ch2 < 32) { S = 96; ch = ch2;       src = g_a4;  }
    else          { S = 24; ch = ch2 - 32;  src = g_a32; }
    float scale = (float)S / (float)HH;
    float fy = (y + 0.5f) * scale - 0.5f;
    float fx = (x + 0.5f) * scale - 0.5f;
    int y0 = (int)floorf(fy); float ty = fy - (float)y0;
    int x0 = (int)floorf(fx); float tx = fx - (float)x0;
    int y0c = max(y0, 0), y1c = min(y0 + 1, S - 1);
    int x0c = max(x0, 0), x1c = min(x0 + 1, S - 1);
    const float* base = src + (long)b * S * S * 32;
    float v00 = base[(y0c*S + x0c)*32 + ch];
    float v01 = base[(y0c*S + x1c)*32 + ch];
    float v10 = base[(y1c*S + x0c)*32 + ch];
    float v11 = base[(y1c*S + x1c)*32 + ch];
    float v = (1.f-ty)*((1.f-tx)*v00 + tx*v01) + ty*((1.f-tx)*v10 + tx*v11);
    g_X[((long)(b*HH + y)*WW + x)*96 + 32 + ch2] = v;
}

// ---------------- conv3x3 (96->96) + ReLU, tf32 mma implicit GEMM ----------------
// block 384 thr (12 warps), 16x16 px tile. M=256 (16 m-tiles=py rows), N=96 (12 n-tiles).
// warp grid: mq = w&3 (4 m-tiles each), nq = w>>2 (4 n-tiles each).
#define CTILE 328   // ci stride in tile smem (==8 mod 32 -> conflict-free A frags)
#define CONV_SMEM (16*CTILE + 18*12*32*2)   // 5248 + 13824 = 19072 floats

__global__ void __launch_bounds__(384, 1)
conv3x3_k(const float* __restrict__ wf, const float* __restrict__ bf) {
    extern __shared__ float cs[];
    float* tile = cs;                          // 16 ci * CTILE
    unsigned* wsf = (unsigned*)(cs + 16*CTILE); // [18 ks][12 nt][32 lanes][2]

    int t = threadIdx.x;
    int lane = t & 31, w = t >> 5;
    int gid = lane >> 2, c4 = lane & 3;
    int mq = w & 3, nq = w >> 2;
    int bx = blockIdx.x, by = blockIdx.y, b = blockIdx.z;

    float acc[4][4][4];
    #pragma unroll
    for (int j = 0; j < 4; j++)
        #pragma unroll
        for (int n = 0; n < 4; n++)
            #pragma unroll
            for (int r = 0; r < 4; r++) acc[j][n][r] = 0.f;

    #pragma unroll 1
    for (int c0 = 0; c0 < 96; c0 += 16) {
        __syncthreads();
        // stage input tile (zero pad borders)
        for (int idx = t; idx < 16*324; idx += 384) {
            int ci = idx / 324;
            int rem = idx - ci*324;
            int yy = rem / 18, xx = rem - yy*18;
            int gy = by*16 + yy - 1, gx = bx*16 + xx - 1;
            float v = 0.f;
            if (gy >= 0 && gy < HH && gx >= 0 && gx < WW)
                v = g_X[((long)(b*HH + gy)*WW + gx)*96 + c0 + ci];
            tile[ci*CTILE + yy*18 + xx] = v;
        }
        // stage weights pre-swizzled into fragment order (tf32 bits)
        for (int i = t; i < 18*12*32; i += 384) {
            int ks = i / 384;
            int rem = i - ks*384;
            int nt = rem >> 5;
            int l = rem & 31;
            int g = l >> 2, c = l & 3;
            int tap = ks >> 1, s = ks & 1;
            int ci0 = s*8 + c;
            const float* wp = &wf[(tap*96 + c0 + ci0)*96 + nt*8 + g];
            wsf[i*2 + 0] = cvt_tf32(wp[0]);
            wsf[i*2 + 1] = cvt_tf32(wp[4*96]);
        }
        __syncthreads();

        #pragma unroll 1
        for (int tap = 0; tap < 9; tap++) {
            int ky = tap / 3, kx = tap - ky*3;
            #pragma unroll
            for (int s = 0; s < 2; s++) {
                uint2 bb[4];
                const uint2* wrow = ((const uint2*)wsf) + ((tap*2 + s)*12 + nq*4)*32 + lane;
                #pragma unroll
                for (int n = 0; n < 4; n++) bb[n] = wrow[n*32];
                #pragma unroll
                for (int j = 0; j < 4; j++) {
                    int py = mq*4 + j;
                    const float* ap = &tile[(s*8 + c4)*CTILE + (py + ky)*18 + gid + kx];
                    unsigned a0 = cvt_tf32(ap[0]);
                    unsigned a1 = cvt_tf32(ap[8]);
                    unsigned a2 = cvt_tf32(ap[4*CTILE]);
                    unsigned a3 = cvt_tf32(ap[4*CTILE + 8]);
                    #pragma unroll
                    for (int n = 0; n < 4; n++)
                        mma_tf32(acc[j][n][0], acc[j][n][1], acc[j][n][2], acc[j][n][3],
                                 a0, a1, a2, a3, bb[n].x, bb[n].y);
                }
            }
        }
    }
    // epilogue: bias + relu, write g_aspp
    float bv[4][2];
    #pragma unroll
    for (int n = 0; n < 4; n++) {
        int ch0 = (nq*4 + n)*8 + 2*c4;
        bv[n][0] = bf[ch0];
        bv[n][1] = bf[ch0 + 1];
    }
    #pragma unroll
    for (int j = 0; j < 4; j++) {
        int gy = by*16 + mq*4 + j;
        int gx0 = bx*16 + gid;
        #pragma unroll
        for (int n = 0; n < 4; n++) {
            int ch0 = (nq*4 + n)*8 + 2*c4;
            float2 v0, v1;
            v0.x = fmaxf(acc[j][n][0] + bv[n][0], 0.f);
            v0.y = fmaxf(acc[j][n][1] + bv[n][1], 0.f);
            v1.x = fmaxf(acc[j][n][2] + bv[n][0], 0.f);
            v1.y = fmaxf(acc[j][n][3] + bv[n][1], 0.f);
            *(float2*)&g_aspp[((long)(b*HH + gy)*WW + gx0)*96 + ch0] = v0;
            *(float2*)&g_aspp[((long)(b*HH + gy)*WW + gx0 + 8)*96 + ch0] = v1;
        }
    }
}

// ---------------- query kernel: gather + MLP (tf32 mma) + blend ----------------
// 256 thr (8 warps); tile = 32 queries x 4 corners = 128 rows. warp w owns rows w*16..+15.
// sA stride 108 (==12 mod 32 -> conflict-free A frags). Weights fragment-swizzled.
#define ASTR 108
#define QS_W0F 0                       // 13*8*32*2 = 6656
#define QS_W1F 6656                    // 8*8*32*2 = 4096
#define QS_B0  10752
#define QS_B1  10816
#define QS_W2  10880
#define QS_A   10944                   // 128*108 = 13824
#define QS_AREA (QS_A + 13824)
#define QS_PRED (QS_AREA + 128)
#define QS_PART (QS_PRED + 128)
#define QS_OFF  (QS_PART + 256)
#define QS_TOTAL (QS_OFF + 128)        // 25408 floats = 101632 B

__global__ void __launch_bounds__(256, 2)
query_k(const float* __restrict__ coords, const float* __restrict__ cells,
        const float* __restrict__ mw0, const float* __restrict__ mb0,
        const float* __restrict__ mw1, const float* __restrict__ mb1,
        const float* __restrict__ mw2, const float* __restrict__ mb2,
        float* __restrict__ out) {
    extern __shared__ float qs[];
    unsigned* sW0f = (unsigned*)(qs + QS_W0F);
    unsigned* sW1f = (unsigned*)(qs + QS_W1F);
    float* sB0 = qs + QS_B0;
    float* sB1 = qs + QS_B1;
    float* sW2 = qs + QS_W2;
    float* sA  = qs + QS_A;
    float* sArea = qs + QS_AREA;
    float* sPred = qs + QS_PRED;
    float* sPart = qs + QS_PART;
    int*   sOff  = (int*)(qs + QS_OFF);
    __shared__ float sB2;

    int t = threadIdx.x;
    int lane = t & 31, w = t >> 5;
    int gid = lane >> 2, c4 = lane & 3;
    int stripe = w * 16;

    // stage weights in fragment order (tf32 bits)
    for (int i = t; i < 13*8*32; i += 256) {
        int ks = i >> 8;
        int rem = i & 255;
        int nt = rem >> 5;
        int l = rem & 31;
        int g = l >> 2, c = l & 3;
        int k0 = ks*8 + c, k1 = k0 + 4;
        int n = nt*8 + g;
        float v0 = (k0 < 102) ? mw0[k0*64 + n] : 0.f;
        float v1 = (k1 < 102) ? mw0[k1*64 + n] : 0.f;
        sW0f[i*2 + 0] = cvt_tf32(v0);
        sW0f[i*2 + 1] = cvt_tf32(v1);
    }
    for (int i = t; i < 8*8*32; i += 256) {
        int ks = i >> 8;
        int rem = i & 255;
        int nt = rem >> 5;
        int l = rem & 31;
        int g = l >> 2, c = l & 3;
        int k0 = ks*8 + c;
        int n = nt*8 + g;
        sW1f[i*2 + 0] = cvt_tf32(mw1[k0*64 + n]);
        sW1f[i*2 + 1] = cvt_tf32(mw1[(k0 + 4)*64 + n]);
    }
    if (t < 64) { sB0[t] = mb0[t]; sB1[t] = mb1[t]; sW2[t] = mw2[t]; }
    if (t == 0) sB2 = mb2[0];
    __syncthreads();

    const int NT = (BB*HQ*HQ) / 32;   // 9216 tiles

    for (int tileI = blockIdx.x; tileI < NT; tileI += gridDim.x) {
        // ---- Phase A: per-row meta (exact fp32) ----
        if (t < 128) {
            int row = t;
            int q = tileI*32 + (row >> 2);
            int corner = row & 3;
            int b = q / (HQ*HQ);
            float cy = coords[q*2 + 0], cx = coords[q*2 + 1];
            float cly = cells[q*2 + 0], clx = cells[q*2 + 1];
            float vy = (corner & 2) ? 1.f : -1.f;
            float vx = (corner & 1) ? 1.f : -1.f;
            float yc = cy + vy * (1.f/(float)HH) + EPSF;
            float xc = cx + vx * (1.f/(float)WW) + EPSF;
            yc = fminf(fmaxf(yc, -1.f + EPSF), 1.f - EPSF);
            xc = fminf(fmaxf(xc, -1.f + EPSF), 1.f - EPSF);
            int iy = (int)rintf((yc + 1.f) * ((float)HH * 0.5f) - 0.5f);
            int ix = (int)rintf((xc + 1.f) * ((float)WW * 0.5f) - 0.5f);
            iy = min(max(iy, 0), HH - 1);
            ix = min(max(ix, 0), WW - 1);
            float sy = (((float)iy + 0.5f) / (float)HH) * 2.f - 1.f;
            float sx = (((float)ix + 0.5f) / (float)WW) * 2.f - 1.f;
            float ry = (cy - sy) * (float)HH;
            float rx = (cx - sx) * (float)WW;
            sA[row*ASTR +  96] = ry;
            sA[row*ASTR +  97] = rx;
            sA[row*ASTR +  98] = cy;
            sA[row*ASTR +  99] = cx;
            sA[row*ASTR + 100] = cly * (float)HH;
            sA[row*ASTR + 101] = clx * (float)WW;
            sA[row*ASTR + 102] = 0.f;
            sA[row*ASTR + 103] = 0.f;
            sArea[row] = fabsf(ry * rx) + EPSF;
            sOff[row] = ((b*HH + iy)*WW + ix) * 96;
        }
        __syncthreads();
        // ---- Phase B: gather features ----
        {
            int row = t >> 1, half = t & 1;
            const float4* src = (const float4*)(g_aspp + sOff[row] + half*48);
            float4* dst = (float4*)&sA[row*ASTR + half*48];
            #pragma unroll
            for (int i = 0; i < 12; i++) dst[i] = src[i];
        }
        __syncthreads();

        // ---- GEMM1: [128x104] @ [104x64] tf32 mma ----
        float acc[8][4];
        #pragma unroll
        for (int n = 0; n < 8; n++)
            #pragma unroll
            for (int r = 0; r < 4; r++) acc[n][r] = 0.f;
        #pragma unroll 1
        for (int ks = 0; ks < 13; ks++) {
            const float* ap = &sA[(stripe + gid)*ASTR + ks*8 + c4];
            unsigned a0 = cvt_tf32(ap[0]);
            unsigned a1 = cvt_tf32(ap[8*ASTR]);
            unsigned a2 = cvt_tf32(ap[4]);
            unsigned a3 = cvt_tf32(ap[8*ASTR + 4]);
            const uint2* wrow = ((const uint2*)sW0f) + (ks*8)*32 + lane;
            #pragma unroll
            for (int n = 0; n < 8; n++) {
                uint2 bb = wrow[n*32];
                mma_tf32(acc[n][0], acc[n][1], acc[n][2], acc[n][3],
                         a0, a1, a2, a3, bb.x, bb.y);
            }
        }
        __syncwarp();
        #pragma unroll
        for (int n = 0; n < 8; n++) {
            int col = n*8 + 2*c4;
            int r0 = stripe + gid;
            sA[r0*ASTR + col]       = fmaxf(acc[n][0] + sB0[col],     0.f);
            sA[r0*ASTR + col + 1]   = fmaxf(acc[n][1] + sB0[col + 1], 0.f);
            sA[(r0+8)*ASTR + col]   = fmaxf(acc[n][2] + sB0[col],     0.f);
            sA[(r0+8)*ASTR + col+1] = fmaxf(acc[n][3] + sB0[col + 1], 0.f);
        }
        __syncwarp();

        // ---- GEMM2: [128x64] @ [64x64] tf32 mma ----
        #pragma unroll
        for (int n = 0; n < 8; n++)
            #pragma unroll
            for (int r = 0; r < 4; r++) acc[n][r] = 0.f;
        #pragma unroll 1
        for (int ks = 0; ks < 8; ks++) {
            const float* ap = &sA[(stripe + gid)*ASTR + ks*8 + c4];
            unsigned a0 = cvt_tf32(ap[0]);
            unsigned a1 = cvt_tf32(ap[8*ASTR]);
            unsigned a2 = cvt_tf32(ap[4]);
            unsigned a3 = cvt_tf32(ap[8*ASTR + 4]);
            const uint2* wrow = ((const uint2*)sW1f) + (ks*8)*32 + lane;
            #pragma unroll
            for (int n = 0; n < 8; n++) {
                uint2 bb = wrow[n*32];
                mma_tf32(acc[n][0], acc[n][1], acc[n][2], acc[n][3],
                         a0, a1, a2, a3, bb.x, bb.y);
            }
        }
        __syncwarp();
        #pragma unroll
        for (int n = 0; n < 8; n++) {
            int col = n*8 + 2*c4;
            int r0 = stripe + gid;
            sA[r0*ASTR + col]       = fmaxf(acc[n][0] + sB1[col],     0.f);
            sA[r0*ASTR + col + 1]   = fmaxf(acc[n][1] + sB1[col + 1], 0.f);
            sA[(r0+8)*ASTR + col]   = fmaxf(acc[n][2] + sB1[col],     0.f);
            sA[(r0+8)*ASTR + col+1] = fmaxf(acc[n][3] + sB1[col + 1], 0.f);
        }
        __syncthreads();

        // ---- GEMM3: [128x64] @ [64x1] exact fp32 ----
        {
            int row = t >> 1, half = t & 1;
            float s = 0.f;
            #pragma unroll
            for (int c = 0; c < 32; c++)
                s = fmaf(sA[row*ASTR + half*32 + c], sW2[half*32 + c], s);
            sPart[t] = s;
        }
        __syncthreads();
        if (t < 128) sPred[t] = sPart[2*t] + sPart[2*t + 1] + sB2;
        __syncthreads();
        // ---- blend corners (pred c pairs with area of corner 3-c) ----
        if (t < 32) {
            int q = tileI*32 + t;
            float num = 0.f, den = 0.f;
            #pragma unroll
            for (int c = 0; c < 4; c++) {
                float ar = sArea[t*4 + (3 - c)];
                num = fmaf(sPred[t*4 + c], ar, num);
                den += ar;
            }
            out[q] = num / den;
        }
        __syncthreads();
    }
}

// ---------------- launch ----------------
extern "C" void kernel_launch(void* const* d_in, const int* in_sizes, int n_in,
                              void* d_out, int out_size) {
    const float* feats2  = (const float*)d_in[0];
    const float* feats4  = (const float*)d_in[1];
    const float* feats32 = (const float*)d_in[2];
    const float* coords  = (const float*)d_in[3];
    const float* cells   = (const float*)d_in[4];
    const float* w2  = (const float*)d_in[5];
    const float* b2  = (const float*)d_in[6];
    const float* w4  = (const float*)d_in[7];
    const float* b4  = (const float*)d_in[8];
    const float* w32 = (const float*)d_in[9];
    const float* b32 = (const float*)d_in[10];
    const float* wf  = (const float*)d_in[11];
    const float* bf  = (const float*)d_in[12];
    const float* mw0 = (const float*)d_in[13];
    const float* mb0 = (const float*)d_in[14];
    const float* mw1 = (const float*)d_in[15];
    const float* mb1 = (const float*)d_in[16];
    const float* mw2 = (const float*)d_in[17];
    const float* mb2 = (const float*)d_in[18];
    float* out = (float*)d_out;

    float *pX, *pA4, *pA32;
    cudaGetSymbolAddress((void**)&pX,  g_X);
    cudaGetSymbolAddress((void**)&pA4, g_a4);
    cudaGetSymbolAddress((void**)&pA32, g_a32);

    cudaFuncSetAttribute(conv3x3_k, cudaFuncAttributeMaxDynamicSharedMemorySize, CONV_SMEM * 4);
    cudaFuncSetAttribute(query_k,  cudaFuncAttributeMaxDynamicSharedMemorySize, QS_TOTAL * 4);

    {
        int npix = BB*HH*WW;
        conv1x1_relu_k<<<(npix + 31)/32, 256>>>(feats2, w2, b2, pX, npix, 64, 96, 0);
    }
    {
        int npix = BB*96*96;
        conv1x1_relu_k<<<(npix + 31)/32, 256>>>(feats4, w4, b4, pA4, npix, 96, 32, 0);
    }
    {
        int npix = BB*24*24;
        conv1x1_relu_k<<<(npix + 31)/32, 256>>>(feats32, w32, b32, pA32, npix, 160, 32, 0);
    }
    {
        int total = BB*HH*WW*64;
        upsample_k<<<(total + 255)/256, 256>>>();
    }
    {
        dim3 grid(WW/16, HH/16, BB);
        conv3x3_k<<<grid, 384, CONV_SMEM * 4>>>(wf, bf);
    }
    {
        query_k<<<296, 256, QS_TOTAL * 4>>>(coords, cells, mw0, mb0, mw1, mb1, mw2, mb2, out);
    }
}

// round 5
// speedup vs baseline: 2.4628x; 1.2201x over previous
#include <cuda_runtime.h>
#include <math.h>

#define BB 2
#define HH 192
#define WW 192
#define HQ 384
#define EPSF 1e-7f
#define NP (BB*HH*WW)   // 73728 pixels

// ---- tf32 mma helpers ----
__device__ __forceinline__ unsigned cvt_tf32(float f) {
    unsigned r; asm("cvt.rna.tf32.f32 %0, %1;" : "=r"(r) : "f"(f)); return r;
}
__device__ __forceinline__ void mma_tf32(float& c0, float& c1, float& c2, float& c3,
                                         unsigned a0, unsigned a1, unsigned a2, unsigned a3,
                                         unsigned b0, unsigned b1) {
    asm("mma.sync.aligned.m16n8k8.row.col.f32.tf32.tf32.f32 "
        "{%0,%1,%2,%3},{%4,%5,%6,%7},{%8,%9},{%0,%1,%2,%3};"
        : "+f"(c0), "+f"(c1), "+f"(c2), "+f"(c3)
        : "r"(a0), "r"(a1), "r"(a2), "r"(a3), "r"(b0), "r"(b1));
}

// ---------------- scratch ----------------
__device__ float g_a4 [BB*96*96*32];
__device__ float g_a32[BB*24*24*32];
__device__ float g_X  [96*NP];         // PLANAR: [ch][b*H*W + y*W + x]
__device__ float g_aspp[NP*96];        // interleaved: [pixel][96]

// ---------------- conv1x1 + ReLU for feats2 (64->32), planar output ----------------
__global__ void conv1x1_feats2_k(const float* __restrict__ in,
                                 const float* __restrict__ w,
                                 const float* __restrict__ bias,
                                 float* __restrict__ outp) {
    __shared__ float sw[64*32];
    __shared__ float sb[32];
    __shared__ float sin[32*65];
    int t = threadIdx.x;
    for (int i = t; i < 64*32; i += 256) sw[i] = w[i];
    if (t < 32) sb[t] = bias[t];
    int px0 = blockIdx.x * 32;
    // stage 32 px x 64 ch coalesced
    const float4* ip4 = (const float4*)(in + (long)px0 * 64);
    for (int i = t; i < 512; i += 256) {
        float4 v = ip4[i];
        int px = i >> 4;
        int ci = (i & 15) * 4;
        sin[px*65 + ci + 0] = v.x;
        sin[px*65 + ci + 1] = v.y;
        sin[px*65 + ci + 2] = v.z;
        sin[px*65 + ci + 3] = v.w;
    }
    __syncthreads();
    int pxl = t & 31;
    int co = (t >> 5) * 4;
    float a0 = 0.f, a1 = 0.f, a2 = 0.f, a3 = 0.f;
    #pragma unroll
    for (int ci = 0; ci < 64; ci++) {
        float xv = sin[pxl*65 + ci];
        float4 wv = *(const float4*)&sw[ci*32 + co];
        a0 = fmaf(xv, wv.x, a0);
        a1 = fmaf(xv, wv.y, a1);
        a2 = fmaf(xv, wv.z, a2);
        a3 = fmaf(xv, wv.w, a3);
    }
    int gpx = px0 + pxl;
    outp[(co+0)*NP + gpx] = fmaxf(a0 + sb[co+0], 0.f);
    outp[(co+1)*NP + gpx] = fmaxf(a1 + sb[co+1], 0.f);
    outp[(co+2)*NP + gpx] = fmaxf(a2 + sb[co+2], 0.f);
    outp[(co+3)*NP + gpx] = fmaxf(a3 + sb[co+3], 0.f);
}

// ---------------- conv1x1 + ReLU (interleaved out, for a4/a32) ----------------
__global__ void conv1x1_relu_k(const float* __restrict__ in,
                               const float* __restrict__ w,
                               const float* __restrict__ bias,
                               float* __restrict__ out,
                               int npix, int Cin) {
    __shared__ float sw[160*32];
    __shared__ float sb[32];
    int tid = threadIdx.x;
    for (int i = tid; i < Cin*32; i += blockDim.x) sw[i] = w[i];
    if (tid < 32) sb[tid] = bias[tid];
    __syncthreads();
    int px = blockIdx.x * 32 + (tid >> 3);
    int co = (tid & 7) * 4;
    if (px >= npix) return;
    const float* ip = in + (long)px * Cin;
    float a0 = 0.f, a1 = 0.f, a2 = 0.f, a3 = 0.f;
    for (int ci = 0; ci < Cin; ci++) {
        float xv = ip[ci];
        float4 wv = *(const float4*)&sw[ci*32 + co];
        a0 = fmaf(xv, wv.x, a0);
        a1 = fmaf(xv, wv.y, a1);
        a2 = fmaf(xv, wv.z, a2);
        a3 = fmaf(xv, wv.w, a3);
    }
    float* op = out + (long)px * 32 + co;
    op[0] = fmaxf(a0 + sb[co+0], 0.f);
    op[1] = fmaxf(a1 + sb[co+1], 0.f);
    op[2] = fmaxf(a2 + sb[co+2], 0.f);
    op[3] = fmaxf(a3 + sb[co+3], 0.f);
}

// ---------------- bilinear upsample -> planar g_X channels 32..95 ----------------
__global__ void upsample_k() {
    int idx = blockIdx.x * blockDim.x + threadIdx.x;
    const int total = 64*BB*HH*WW;
    if (idx >= total) return;
    int x = idx % WW;
    int tmp = idx / WW;
    int y = tmp % HH; tmp /= HH;
    int b = tmp % BB;
    int ch2 = tmp / BB;

    int S, ch;
    const float* src;
    if (ch2 < 32) { S = 96; ch = ch2;       src = g_a4;  }
    else          { S = 24; ch = ch2 - 32;  src = g_a32; }
    float scale = (float)S / (float)HH;
    float fy = (y + 0.5f) * scale - 0.5f;
    float fx = (x + 0.5f) * scale - 0.5f;
    int y0 = (int)floorf(fy); float ty = fy - (float)y0;
    int x0 = (int)floorf(fx); float tx = fx - (float)x0;
    int y0c = max(y0, 0), y1c = min(y0 + 1, S - 1);
    int x0c = max(x0, 0), x1c = min(x0 + 1, S - 1);
    const float* base = src + (long)b * S * S * 32;
    float v00 = base[(y0c*S + x0c)*32 + ch];
    float v01 = base[(y0c*S + x1c)*32 + ch];
    float v10 = base[(y1c*S + x0c)*32 + ch];
    float v11 = base[(y1c*S + x1c)*32 + ch];
    float v = (1.f-ty)*((1.f-tx)*v00 + tx*v01) + ty*((1.f-tx)*v10 + tx*v11);
    g_X[(32 + ch2)*NP + (b*HH + y)*WW + x] = v;
}

// ---------------- conv3x3 (96->96) + ReLU, tf32 mma, planar input ----------------
#define CTILE 328
#define CONV_SMEM (16*CTILE + 18*12*32*2)

__global__ void __launch_bounds__(384, 1)
conv3x3_k(const float* __restrict__ wf, const float* __restrict__ bf) {
    extern __shared__ float cs[];
    float* tile = cs;
    unsigned* wsf = (unsigned*)(cs + 16*CTILE);

    int t = threadIdx.x;
    int lane = t & 31, w = t >> 5;
    int gid = lane >> 2, c4 = lane & 3;
    int mq = w & 3, nq = w >> 2;
    int bx = blockIdx.x, by = blockIdx.y, b = blockIdx.z;

    float acc[4][4][4];
    #pragma unroll
    for (int j = 0; j < 4; j++)
        #pragma unroll
        for (int n = 0; n < 4; n++)
            #pragma unroll
            for (int r = 0; r < 4; r++) acc[j][n][r] = 0.f;

    #pragma unroll 1
    for (int c0 = 0; c0 < 96; c0 += 16) {
        __syncthreads();
        // stage input tile from PLANAR layout (coalesced rows)
        for (int idx = t; idx < 16*324; idx += 384) {
            int ci = idx / 324;
            int rem = idx - ci*324;
            int yy = rem / 18, xx = rem - yy*18;
            int gy = by*16 + yy - 1, gx = bx*16 + xx - 1;
            float v = 0.f;
            if (gy >= 0 && gy < HH && gx >= 0 && gx < WW)
                v = g_X[(long)(c0 + ci)*NP + (b*HH + gy)*WW + gx];
            tile[ci*CTILE + yy*18 + xx] = v;
        }
        // stage weights fragment-swizzled
        for (int i = t; i < 18*12*32; i += 384) {
            int ks = i / 384;
            int rem = i - ks*384;
            int nt = rem >> 5;
            int l = rem & 31;
            int g = l >> 2, c = l & 3;
            int tap = ks >> 1, s = ks & 1;
            int ci0 = s*8 + c;
            const float* wp = &wf[(tap*96 + c0 + ci0)*96 + nt*8 + g];
            wsf[i*2 + 0] = cvt_tf32(wp[0]);
            wsf[i*2 + 1] = cvt_tf32(wp[4*96]);
        }
        __syncthreads();

        #pragma unroll 1
        for (int tap = 0; tap < 9; tap++) {
            int ky = tap / 3, kx = tap - ky*3;
            #pragma unroll
            for (int s = 0; s < 2; s++) {
                uint2 bb[4];
                const uint2* wrow = ((const uint2*)wsf) + ((tap*2 + s)*12 + nq*4)*32 + lane;
                #pragma unroll
                for (int n = 0; n < 4; n++) bb[n] = wrow[n*32];
                #pragma unroll
                for (int j = 0; j < 4; j++) {
                    int py = mq*4 + j;
                    const float* ap = &tile[(s*8 + c4)*CTILE + (py + ky)*18 + gid + kx];
                    unsigned a0 = cvt_tf32(ap[0]);
                    unsigned a1 = cvt_tf32(ap[8]);
                    unsigned a2 = cvt_tf32(ap[4*CTILE]);
                    unsigned a3 = cvt_tf32(ap[4*CTILE + 8]);
                    #pragma unroll
                    for (int n = 0; n < 4; n++)
                        mma_tf32(acc[j][n][0], acc[j][n][1], acc[j][n][2], acc[j][n][3],
                                 a0, a1, a2, a3, bb[n].x, bb[n].y);
                }
            }
        }
    }
    float bv[4][2];
    #pragma unroll
    for (int n = 0; n < 4; n++) {
        int ch0 = (nq*4 + n)*8 + 2*c4;
        bv[n][0] = bf[ch0];
        bv[n][1] = bf[ch0 + 1];
    }
    #pragma unroll
    for (int j = 0; j < 4; j++) {
        int gy = by*16 + mq*4 + j;
        int gx0 = bx*16 + gid;
        #pragma unroll
        for (int n = 0; n < 4; n++) {
            int ch0 = (nq*4 + n)*8 + 2*c4;
            float2 v0, v1;
            v0.x = fmaxf(acc[j][n][0] + bv[n][0], 0.f);
            v0.y = fmaxf(acc[j][n][1] + bv[n][1], 0.f);
            v1.x = fmaxf(acc[j][n][2] + bv[n][0], 0.f);
            v1.y = fmaxf(acc[j][n][3] + bv[n][1], 0.f);
            *(float2*)&g_aspp[((long)(b*HH + gy)*WW + gx0)*96 + ch0] = v0;
            *(float2*)&g_aspp[((long)(b*HH + gy)*WW + gx0 + 8)*96 + ch0] = v1;
        }
    }
}

// ---------------- query kernel: warp-synchronous gather + MLP + blend ----------------
#define ASTR 108
#define QS_W0F 0                       // 13*8*32*2 = 6656
#define QS_W1F 6656                    // 4096
#define QS_B0  10752
#define QS_B1  10816
#define QS_W2  10880
#define QS_A   10944                   // 128*108 = 13824
#define QS_AREA (QS_A + 13824)         // 8 warps * 16
#define QS_PRED (QS_AREA + 128)        // 8 warps * 16
#define QS_TOTAL (QS_PRED + 128)       // 25024 floats = 100096 B

__global__ void __launch_bounds__(256, 2)
query_k(const float* __restrict__ coords, const float* __restrict__ cells,
        const float* __restrict__ mw0, const float* __restrict__ mb0,
        const float* __restrict__ mw1, const float* __restrict__ mb1,
        const float* __restrict__ mw2, const float* __restrict__ mb2,
        float* __restrict__ out) {
    extern __shared__ float qs[];
    unsigned* sW0f = (unsigned*)(qs + QS_W0F);
    unsigned* sW1f = (unsigned*)(qs + QS_W1F);
    float* sB0 = qs + QS_B0;
    float* sB1 = qs + QS_B1;
    float* sW2 = qs + QS_W2;
    float* sA  = qs + QS_A;
    float* sAreaW = qs + QS_AREA;
    float* sPredW = qs + QS_PRED;
    __shared__ float sB2;

    int t = threadIdx.x;
    int lane = t & 31, w = t >> 5;
    int gid = lane >> 2, c4 = lane & 3;
    int stripe = w * 16;

    // stage weights in fragment order
    for (int i = t; i < 13*8*32; i += 256) {
        int ks = i >> 8;
        int rem = i & 255;
        int nt = rem >> 5;
        int l = rem & 31;
        int g = l >> 2, c = l & 3;
        int k0 = ks*8 + c, k1 = k0 + 4;
        int n = nt*8 + g;
        float v0 = (k0 < 102) ? mw0[k0*64 + n] : 0.f;
        float v1 = (k1 < 102) ? mw0[k1*64 + n] : 0.f;
        sW0f[i*2 + 0] = cvt_tf32(v0);
        sW0f[i*2 + 1] = cvt_tf32(v1);
    }
    for (int i = t; i < 8*8*32; i += 256) {
        int ks = i >> 8;
        int rem = i & 255;
        int nt = rem >> 5;
        int l = rem & 31;
        int g = l >> 2, c = l & 3;
        int k0 = ks*8 + c;
        int n = nt*8 + g;
        sW1f[i*2 + 0] = cvt_tf32(mw1[k0*64 + n]);
        sW1f[i*2 + 1] = cvt_tf32(mw1[(k0 + 4)*64 + n]);
    }
    if (t < 64) { sB0[t] = mb0[t]; sB1[t] = mb1[t]; sW2[t] = mw2[t]; }
    if (t == 0) sB2 = mb2[0];
    __syncthreads();

    // per-thread constants
    float b2v = sB2;
    float w2r[8][2];
    #pragma unroll
    for (int n = 0; n < 8; n++) {
        int col = n*8 + 2*c4;
        w2r[n][0] = sW2[col];
        w2r[n][1] = sW2[col + 1];
    }

    const int NT = (BB*HQ*HQ) / 32;   // 9216 tiles

    for (int tileI = blockIdx.x; tileI < NT; tileI += gridDim.x) {
        // ---- Phase A: meta (lanes 0..15, one row each) ----
        int offR = 0;
        if (lane < 16) {
            int row = stripe + lane;
            int q = tileI*32 + (row >> 2);
            int corner = row & 3;
            int b = q / (HQ*HQ);
            float cy = coords[q*2 + 0], cx = coords[q*2 + 1];
            float cly = cells[q*2 + 0], clx = cells[q*2 + 1];
            float vy = (corner & 2) ? 1.f : -1.f;
            float vx = (corner & 1) ? 1.f : -1.f;
            float yc = cy + vy * (1.f/(float)HH) + EPSF;
            float xc = cx + vx * (1.f/(float)WW) + EPSF;
            yc = fminf(fmaxf(yc, -1.f + EPSF), 1.f - EPSF);
            xc = fminf(fmaxf(xc, -1.f + EPSF), 1.f - EPSF);
            int iy = (int)rintf((yc + 1.f) * ((float)HH * 0.5f) - 0.5f);
            int ix = (int)rintf((xc + 1.f) * ((float)WW * 0.5f) - 0.5f);
            iy = min(max(iy, 0), HH - 1);
            ix = min(max(ix, 0), WW - 1);
            float sy = (((float)iy + 0.5f) / (float)HH) * 2.f - 1.f;
            float sx = (((float)ix + 0.5f) / (float)WW) * 2.f - 1.f;
            float ry = (cy - sy) * (float)HH;
            float rx = (cx - sx) * (float)WW;
            sA[row*ASTR +  96] = ry;
            sA[row*ASTR +  97] = rx;
            sA[row*ASTR +  98] = cy;
            sA[row*ASTR +  99] = cx;
            sA[row*ASTR + 100] = cly * (float)HH;
            sA[row*ASTR + 101] = clx * (float)WW;
            sA[row*ASTR + 102] = 0.f;
            sA[row*ASTR + 103] = 0.f;
            sAreaW[w*16 + lane] = fabsf(ry * rx) + EPSF;
            offR = ((b*HH + iy)*WW + ix) * 96;
        }
        __syncwarp();
        // ---- Phase B: gather (2 lanes per row) ----
        {
            int off = __shfl_sync(0xffffffff, offR, lane >> 1);
            int row = stripe + (lane >> 1);
            int half = lane & 1;
            const float4* src = (const float4*)(g_aspp + off + half*48);
            float4* dst = (float4*)&sA[row*ASTR + half*48];
            #pragma unroll
            for (int i = 0; i < 12; i++) dst[i] = src[i];
        }
        __syncwarp();

        // ---- GEMM1: [16x104] @ [104x64] per warp ----
        float acc[8][4];
        #pragma unroll
        for (int n = 0; n < 8; n++)
            #pragma unroll
            for (int r = 0; r < 4; r++) acc[n][r] = 0.f;
        #pragma unroll 1
        for (int ks = 0; ks < 13; ks++) {
            const float* ap = &sA[(stripe + gid)*ASTR + ks*8 + c4];
            unsigned a0 = cvt_tf32(ap[0]);
            unsigned a1 = cvt_tf32(ap[8*ASTR]);
            unsigned a2 = cvt_tf32(ap[4]);
            unsigned a3 = cvt_tf32(ap[8*ASTR + 4]);
            const uint2* wrow = ((const uint2*)sW0f) + (ks*8)*32 + lane;
            #pragma unroll
            for (int n = 0; n < 8; n++) {
                uint2 bb = wrow[n*32];
                mma_tf32(acc[n][0], acc[n][1], acc[n][2], acc[n][3],
                         a0, a1, a2, a3, bb.x, bb.y);
            }
        }
        __syncwarp();
        #pragma unroll
        for (int n = 0; n < 8; n++) {
            int col = n*8 + 2*c4;
            int r0 = stripe + gid;
            sA[r0*ASTR + col]       = fmaxf(acc[n][0] + sB0[col],     0.f);
            sA[r0*ASTR + col + 1]   = fmaxf(acc[n][1] + sB0[col + 1], 0.f);
            sA[(r0+8)*ASTR + col]   = fmaxf(acc[n][2] + sB0[col],     0.f);
            sA[(r0+8)*ASTR + col+1] = fmaxf(acc[n][3] + sB0[col + 1], 0.f);
        }
        __syncwarp();

        // ---- GEMM2: [16x64] @ [64x64] per warp ----
        #pragma unroll
        for (int n = 0; n < 8; n++)
            #pragma unroll
            for (int r = 0; r < 4; r++) acc[n][r] = 0.f;
        #pragma unroll 1
        for (int ks = 0; ks < 8; ks++) {
            const float* ap = &sA[(stripe + gid)*ASTR + ks*8 + c4];
            unsigned a0 = cvt_tf32(ap[0]);
            unsigned a1 = cvt_tf32(ap[8*ASTR]);
            unsigned a2 = cvt_tf32(ap[4]);
            unsigned a3 = cvt_tf32(ap[8*ASTR + 4]);
            const uint2* wrow = ((const uint2*)sW1f) + (ks*8)*32 + lane;
            #pragma unroll
            for (int n = 0; n < 8; n++) {
                uint2 bb = wrow[n*32];
                mma_tf32(acc[n][0], acc[n][1], acc[n][2], acc[n][3],
                         a0, a1, a2, a3, bb.x, bb.y);
            }
        }
        // ---- fused GEMM3: h2 = relu(acc+b1); pred = dot(h2, w2) via shfl ----
        {
            float p0 = 0.f, p1 = 0.f;
            #pragma unroll
            for (int n = 0; n < 8; n++) {
                int col = n*8 + 2*c4;
                float h00 = fmaxf(acc[n][0] + sB1[col],     0.f);
                float h01 = fmaxf(acc[n][1] + sB1[col + 1], 0.f);
                float h10 = fmaxf(acc[n][2] + sB1[col],     0.f);
                float h11 = fmaxf(acc[n][3] + sB1[col + 1], 0.f);
                p0 = fmaf(h00, w2r[n][0], fmaf(h01, w2r[n][1], p0));
                p1 = fmaf(h10, w2r[n][0], fmaf(h11, w2r[n][1], p1));
            }
            p0 += __shfl_xor_sync(0xffffffff, p0, 1);
            p0 += __shfl_xor_sync(0xffffffff, p0, 2);
            p1 += __shfl_xor_sync(0xffffffff, p1, 1);
            p1 += __shfl_xor_sync(0xffffffff, p1, 2);
            if (c4 == 0) {
                sPredW[w*16 + gid]     = p0 + b2v;
                sPredW[w*16 + gid + 8] = p1 + b2v;
            }
        }
        __syncwarp();
        // ---- blend (lanes 0..3, one query each) ----
        if (lane < 4) {
            float num = 0.f, den = 0.f;
            #pragma unroll
            for (int c = 0; c < 4; c++) {
                float ar = sAreaW[w*16 + lane*4 + (3 - c)];
                num = fmaf(sPredW[w*16 + lane*4 + c], ar, num);
                den += ar;
            }
            out[tileI*32 + w*4 + lane] = num / den;
        }
        __syncwarp();
    }
}

// ---------------- launch ----------------
extern "C" void kernel_launch(void* const* d_in, const int* in_sizes, int n_in,
                              void* d_out, int out_size) {
    const float* feats2  = (const float*)d_in[0];
    const float* feats4  = (const float*)d_in[1];
    const float* feats32 = (const float*)d_in[2];
    const float* coords  = (const float*)d_in[3];
    const float* cells   = (const float*)d_in[4];
    const float* w2  = (const float*)d_in[5];
    const float* b2  = (const float*)d_in[6];
    const float* w4  = (const float*)d_in[7];
    const float* b4  = (const float*)d_in[8];
    const float* w32 = (const float*)d_in[9];
    const float* b32 = (const float*)d_in[10];
    const float* wf  = (const float*)d_in[11];
    const float* bf  = (const float*)d_in[12];
    const float* mw0 = (const float*)d_in[13];
    const float* mb0 = (const float*)d_in[14];
    const float* mw1 = (const float*)d_in[15];
    const float* mb1 = (const float*)d_in[16];
    const float* mw2 = (const float*)d_in[17];
    const float* mb2 = (const float*)d_in[18];
    float* out = (float*)d_out;

    float *pX, *pA4, *pA32;
    cudaGetSymbolAddress((void**)&pX,  g_X);
    cudaGetSymbolAddress((void**)&pA4, g_a4);
    cudaGetSymbolAddress((void**)&pA32, g_a32);

    cudaFuncSetAttribute(conv3x3_k, cudaFuncAttributeMaxDynamicSharedMemorySize, CONV_SMEM * 4);
    cudaFuncSetAttribute(query_k,  cudaFuncAttributeMaxDynamicSharedMemorySize, QS_TOTAL * 4);

    // conv1x1 heads
    conv1x1_feats2_k<<<NP/32, 256>>>(feats2, w2, b2, pX);
    {
        int npix = BB*96*96;
        conv1x1_relu_k<<<(npix + 31)/32, 256>>>(feats4, w4, b4, pA4, npix, 96);
    }
    {
        int npix = BB*24*24;
        conv1x1_relu_k<<<(npix + 31)/32, 256>>>(feats32, w32, b32, pA32, npix, 160);
    }
    // upsample + concat (planar)
    {
        int total = 64*BB*HH*WW;
        upsample_k<<<(total + 255)/256, 256>>>();
    }
    // conv3x3
    {
        dim3 grid(WW/16, HH/16, BB);
        conv3x3_k<<<grid, 384, CONV_SMEM * 4>>>(wf, bf);
    }
    // query MLP (persistent, warp-synchronous)
    query_k<<<296, 256, QS_TOTAL * 4>>>(coords, cells, mw0, mb0, mw1, mb1, mw2, mb2, out);
}

// round 7
// speedup vs baseline: 2.7707x; 1.1250x over previous
#include <cuda_runtime.h>
#include <math.h>

#define BB 2
#define HH 192
#define WW 192
#define HQ 384
#define EPSF 1e-7f
#define NP (BB*HH*WW)   // 73728 pixels

// ---- tf32 mma helpers ----
__device__ __forceinline__ unsigned cvt_tf32(float f) {
    unsigned r; asm("cvt.rna.tf32.f32 %0, %1;" : "=r"(r) : "f"(f)); return r;
}
__device__ __forceinline__ void mma_tf32(float& c0, float& c1, float& c2, float& c3,
                                         unsigned a0, unsigned a1, unsigned a2, unsigned a3,
                                         unsigned b0, unsigned b1) {
    asm("mma.sync.aligned.m16n8k8.row.col.f32.tf32.tf32.f32 "
        "{%0,%1,%2,%3},{%4,%5,%6,%7},{%8,%9},{%0,%1,%2,%3};"
        : "+f"(c0), "+f"(c1), "+f"(c2), "+f"(c3)
        : "r"(a0), "r"(a1), "r"(a2), "r"(a3), "r"(b0), "r"(b1));
}
__device__ __forceinline__ unsigned smem_u32(const void* p) {
    return (unsigned)__cvta_generic_to_shared(p);
}
__device__ __forceinline__ void cpasync16(unsigned dst, const void* src) {
    asm volatile("cp.async.cg.shared.global [%0], [%1], 16;\n" :: "r"(dst), "l"(src));
}
__device__ __forceinline__ void cpasync4z(unsigned dst, const void* src, int srcsize) {
    asm volatile("cp.async.ca.shared.global [%0], [%1], 4, %2;\n" :: "r"(dst), "l"(src), "r"(srcsize));
}
__device__ __forceinline__ void cpcommit() {
    asm volatile("cp.async.commit_group;\n");
}

// ---------------- scratch ----------------
__device__ float g_a4 [32*BB*96*96];   // planar [ch][b][96][96]
__device__ float g_a32[32*BB*24*24];   // planar [ch][b][24][24]
__device__ float g_X  [96*NP];         // planar [ch][b*H*W + y*W + x]
__device__ float g_aspp[NP*96];        // interleaved [pixel][96]

// ---------------- conv1x1 + ReLU feats2 (64->32), planar out ----------------
__global__ void conv1x1_feats2_k(const float* __restrict__ in,
                                 const float* __restrict__ w,
                                 const float* __restrict__ bias,
                                 float* __restrict__ outp) {
    __shared__ float sw[64*32];
    __shared__ float sb[32];
    __shared__ float sin[32*65];
    int t = threadIdx.x;
    for (int i = t; i < 64*32; i += 256) sw[i] = w[i];
    if (t < 32) sb[t] = bias[t];
    int px0 = blockIdx.x * 32;
    const float4* ip4 = (const float4*)(in + (long)px0 * 64);
    for (int i = t; i < 512; i += 256) {
        float4 v = ip4[i];
        int px = i >> 4;
        int ci = (i & 15) * 4;
        sin[px*65 + ci + 0] = v.x;
        sin[px*65 + ci + 1] = v.y;
        sin[px*65 + ci + 2] = v.z;
        sin[px*65 + ci + 3] = v.w;
    }
    __syncthreads();
    int pxl = t & 31;
    int co = (t >> 5) * 4;
    float a0 = 0.f, a1 = 0.f, a2 = 0.f, a3 = 0.f;
    #pragma unroll
    for (int ci = 0; ci < 64; ci++) {
        float xv = sin[pxl*65 + ci];
        float4 wv = *(const float4*)&sw[ci*32 + co];
        a0 = fmaf(xv, wv.x, a0);
        a1 = fmaf(xv, wv.y, a1);
        a2 = fmaf(xv, wv.z, a2);
        a3 = fmaf(xv, wv.w, a3);
    }
    int gpx = px0 + pxl;
    outp[(co+0)*NP + gpx] = fmaxf(a0 + sb[co+0], 0.f);
    outp[(co+1)*NP + gpx] = fmaxf(a1 + sb[co+1], 0.f);
    outp[(co+2)*NP + gpx] = fmaxf(a2 + sb[co+2], 0.f);
    outp[(co+3)*NP + gpx] = fmaxf(a3 + sb[co+3], 0.f);
}

// ---------------- conv1x1 + ReLU generic -> PLANAR out ----------------
__global__ void conv1x1_planar_k(const float* __restrict__ in,
                                 const float* __restrict__ w,
                                 const float* __restrict__ bias,
                                 float* __restrict__ outp,
                                 int npix, int Cin) {
    __shared__ float sw[160*32];
    __shared__ float sb[32];
    __shared__ float sin[32*161];
    int t = threadIdx.x;
    int cs1 = Cin + 1;
    for (int i = t; i < Cin*32; i += 256) sw[i] = w[i];
    if (t < 32) sb[t] = bias[t];
    int px0 = blockIdx.x * 32;
    for (int i = t; i < 32*Cin; i += 256) {
        int px = i / Cin;
        int ci = i - px*Cin;
        sin[px*cs1 + ci] = in[(long)px0*Cin + i];
    }
    __syncthreads();
    int pxl = t & 31;
    int co = (t >> 5) * 4;
    float a0 = 0.f, a1 = 0.f, a2 = 0.f, a3 = 0.f;
    for (int ci = 0; ci < Cin; ci++) {
        float xv = sin[pxl*cs1 + ci];
        float4 wv = *(const float4*)&sw[ci*32 + co];
        a0 = fmaf(xv, wv.x, a0);
        a1 = fmaf(xv, wv.y, a1);
        a2 = fmaf(xv, wv.z, a2);
        a3 = fmaf(xv, wv.w, a3);
    }
    int gpx = px0 + pxl;
    outp[(co+0)*npix + gpx] = fmaxf(a0 + sb[co+0], 0.f);
    outp[(co+1)*npix + gpx] = fmaxf(a1 + sb[co+1], 0.f);
    outp[(co+2)*npix + gpx] = fmaxf(a2 + sb[co+2], 0.f);
    outp[(co+3)*npix + gpx] = fmaxf(a3 + sb[co+3], 0.f);
}

// ---------------- bilinear upsample (planar in, planar out) ----------------
__global__ void upsample_k() {
    int idx = blockIdx.x * blockDim.x + threadIdx.x;
    const int total = 64*BB*HH*WW;
    if (idx >= total) return;
    int x = idx % WW;
    int tmp = idx / WW;
    int y = tmp % HH; tmp /= HH;
    int b = tmp % BB;
    int ch2 = tmp / BB;

    int S, ch;
    const float* src;
    if (ch2 < 32) { S = 96; ch = ch2;       src = g_a4;  }
    else          { S = 24; ch = ch2 - 32;  src = g_a32; }
    float scale = (float)S / (float)HH;
    float fy = (y + 0.5f) * scale - 0.5f;
    float fx = (x + 0.5f) * scale - 0.5f;
    int y0 = (int)floorf(fy); float ty = fy - (float)y0;
    int x0 = (int)floorf(fx); float tx = fx - (float)x0;
    int y0c = max(y0, 0), y1c = min(y0 + 1, S - 1);
    int x0c = max(x0, 0), x1c = min(x0 + 1, S - 1);
    const float* base = src + ((long)ch*BB + b) * S * S;
    float v00 = base[y0c*S + x0c];
    float v01 = base[y0c*S + x1c];
    float v10 = base[y1c*S + x0c];
    float v11 = base[y1c*S + x1c];
    float v = (1.f-ty)*((1.f-tx)*v00 + tx*v01) + ty*((1.f-tx)*v10 + tx*v11);
    g_X[(32 + ch2)*NP + (b*HH + y)*WW + x] = v;
}

// ---------------- conv3x3 (96->96) + ReLU, tf32 mma, cp.async double-buffer ----------------
#define CTILE 328                       // tile ci stride (==8 mod 32)
#define WSTR  104                       // weight ci stride (==8 mod 32)
#define CBUF  (16*CTILE + 9*16*WSTR)    // 5248 + 14976 = 20224 floats
#define CONV_SMEM (2*CBUF)              // 40448 floats = 161792 B

__global__ void __launch_bounds__(384, 1)
conv3x3_k(const float* __restrict__ wf, const float* __restrict__ bf) {
    extern __shared__ float cs[];
    int t = threadIdx.x;
    int lane = t & 31, w = t >> 5;
    int gid = lane >> 2, c4 = lane & 3;
    int mq = w & 3, nq = w >> 2;
    int bx = blockIdx.x, by = blockIdx.y, b = blockIdx.z;

    float acc[4][4][4];
    #pragma unroll
    for (int j = 0; j < 4; j++)
        #pragma unroll
        for (int n = 0; n < 4; n++)
            #pragma unroll
            for (int r = 0; r < 4; r++) acc[j][n][r] = 0.f;

    // ---- stage chunk helper (cp.async) ----
    auto stage = [&](int c0, float* buf) {
        float* tile = buf;
        float* wb   = buf + 16*CTILE;
        for (int idx = t; idx < 16*324; idx += 384) {
            int ci = idx / 324;
            int rem = idx - ci*324;
            int yy = rem / 18, xx = rem - yy*18;
            int gy = by*16 + yy - 1, gx = bx*16 + xx - 1;
            bool ok = (gy >= 0 && gy < HH && gx >= 0 && gx < WW);
            const float* src = ok ? &g_X[(long)(c0 + ci)*NP + (b*HH + gy)*WW + gx] : &g_X[0];
            cpasync4z(smem_u32(&tile[ci*CTILE + yy*18 + xx]), src, ok ? 4 : 0);
        }
        for (int u = t; u < 3456; u += 384) {      // 9 taps * 16 ci * 24 float4
            int tap = u / 384;
            int r = u - tap*384;
            int ci = r / 24, n4 = r - ci*24;
            cpasync16(smem_u32(&wb[(tap*16 + ci)*WSTR + n4*4]),
                      &wf[(tap*96 + c0 + ci)*96 + n4*4]);
        }
        cpcommit();
    };

    stage(0, cs);
    #pragma unroll 1
    for (int idx = 0; idx < 6; idx++) {
        float* buf = cs + (idx & 1) * CBUF;
        if (idx < 5) {
            stage((idx + 1) * 16, cs + ((idx + 1) & 1) * CBUF);
            asm volatile("cp.async.wait_group 1;\n");
        } else {
            asm volatile("cp.async.wait_group 0;\n");
        }
        __syncthreads();
        float* tile = buf;
        float* wb   = buf + 16*CTILE;

        #pragma unroll 1
        for (int tap = 0; tap < 9; tap++) {
            int ky = tap / 3, kx = tap - ky*3;
            #pragma unroll
            for (int s = 0; s < 2; s++) {
                unsigned bbx[4], bby[4];
                int krow = tap*16 + s*8 + c4;
                #pragma unroll
                for (int n = 0; n < 4; n++) {
                    int col = (nq*4 + n)*8 + gid;
                    bbx[n] = cvt_tf32(wb[krow*WSTR + col]);
                    bby[n] = cvt_tf32(wb[(krow + 4)*WSTR + col]);
                }
                #pragma unroll
                for (int j = 0; j < 4; j++) {
                    int py = mq*4 + j;
                    const float* ap = &tile[(s*8 + c4)*CTILE + (py + ky)*18 + gid + kx];
                    unsigned a0 = cvt_tf32(ap[0]);
                    unsigned a1 = cvt_tf32(ap[8]);
                    unsigned a2 = cvt_tf32(ap[4*CTILE]);
                    unsigned a3 = cvt_tf32(ap[4*CTILE + 8]);
                    #pragma unroll
                    for (int n = 0; n < 4; n++)
                        mma_tf32(acc[j][n][0], acc[j][n][1], acc[j][n][2], acc[j][n][3],
                                 a0, a1, a2, a3, bbx[n], bby[n]);
                }
            }
        }
        __syncthreads();
    }

    float bv[4][2];
    #pragma unroll
    for (int n = 0; n < 4; n++) {
        int ch0 = (nq*4 + n)*8 + 2*c4;
        bv[n][0] = bf[ch0];
        bv[n][1] = bf[ch0 + 1];
    }
    #pragma unroll
    for (int j = 0; j < 4; j++) {
        int gy = by*16 + mq*4 + j;
        int gx0 = bx*16 + gid;
        #pragma unroll
        for (int n = 0; n < 4; n++) {
            int ch0 = (nq*4 + n)*8 + 2*c4;
            float2 v0, v1;
            v0.x = fmaxf(acc[j][n][0] + bv[n][0], 0.f);
            v0.y = fmaxf(acc[j][n][1] + bv[n][1], 0.f);
            v1.x = fmaxf(acc[j][n][2] + bv[n][0], 0.f);
            v1.y = fmaxf(acc[j][n][3] + bv[n][1], 0.f);
            *(float2*)&g_aspp[((long)(b*HH + gy)*WW + gx0)*96 + ch0] = v0;
            *(float2*)&g_aspp[((long)(b*HH + gy)*WW + gx0 + 8)*96 + ch0] = v1;
        }
    }
}

// ---------------- query kernel: cp.async pipelined, warp-synchronous ----------------
#define ASTR 108
#define QROWS 192                        // 12 warps * 16 rows
#define SABUF (QROWS*ASTR)               // 20736 floats per buffer
#define QS_W0F 0
#define QS_W1F 6656
#define QS_B0  10752
#define QS_B1  10816
#define QS_W2  10880
#define QS_A   10944                     // 2 * SABUF
#define QS_AREA (QS_A + 2*SABUF)         // 2 * 192
#define QS_PRED (QS_AREA + 2*QROWS)      // 192
#define QS_TOTAL (QS_PRED + QROWS)       // 52992 floats = 211968 B

__global__ void __launch_bounds__(384, 1)
query_k(const float* __restrict__ coords, const float* __restrict__ cells,
        const float* __restrict__ mw0, const float* __restrict__ mb0,
        const float* __restrict__ mw1, const float* __restrict__ mb1,
        const float* __restrict__ mw2, const float* __restrict__ mb2,
        float* __restrict__ out) {
    extern __shared__ float qs[];
    unsigned* sW0f = (unsigned*)(qs + QS_W0F);
    unsigned* sW1f = (unsigned*)(qs + QS_W1F);
    float* sB0 = qs + QS_B0;
    float* sB1 = qs + QS_B1;
    float* sW2 = qs + QS_W2;
    float* sAreaB = qs + QS_AREA;
    float* sPredW = qs + QS_PRED;
    __shared__ float sB2;

    int t = threadIdx.x;
    int lane = t & 31, w = t >> 5;
    int gid = lane >> 2, c4 = lane & 3;
    int stripe = w * 16;

    for (int i = t; i < 13*8*32; i += 384) {
        int ks = i >> 8;
        int rem = i & 255;
        int nt = rem >> 5;
        int l = rem & 31;
        int g = l >> 2, c = l & 3;
        int k0 = ks*8 + c, k1 = k0 + 4;
        int n = nt*8 + g;
        float v0 = (k0 < 102) ? mw0[k0*64 + n] : 0.f;
        float v1 = (k1 < 102) ? mw0[k1*64 + n] : 0.f;
        sW0f[i*2 + 0] = cvt_tf32(v0);
        sW0f[i*2 + 1] = cvt_tf32(v1);
    }
    for (int i = t; i < 8*8*32; i += 384) {
        int ks = i >> 8;
        int rem = i & 255;
        int nt = rem >> 5;
        int l = rem & 31;
        int g = l >> 2, c = l & 3;
        int k0 = ks*8 + c;
        int n = nt*8 + g;
        sW1f[i*2 + 0] = cvt_tf32(mw1[k0*64 + n]);
        sW1f[i*2 + 1] = cvt_tf32(mw1[(k0 + 4)*64 + n]);
    }
    if (t < 64) { sB0[t] = mb0[t]; sB1[t] = mb1[t]; sW2[t] = mw2[t]; }
    if (t == 0) sB2 = mb2[0];
    __syncthreads();

    float b2v = sB2;
    float w2r[8][2];
    #pragma unroll
    for (int n = 0; n < 8; n++) {
        int col = n*8 + 2*c4;
        w2r[n][0] = sW2[col];
        w2r[n][1] = sW2[col + 1];
    }

    const int NT = (BB*HQ*HQ) / 48;      // 6144 tiles of 48 queries
    const int GS = gridDim.x;

    // ---- meta computation: lanes<16, for local row `lane`, tile T, into buffer nb ----
    auto do_meta = [&](int T, int nb, float2 co, float2 ce) -> int {
        int row = stripe + lane;
        int corner = lane & 3;
        int q = T*48 + w*4 + (lane >> 2);
        int b = q / (HQ*HQ);
        float cy = co.x, cx = co.y;
        float vy = (corner & 2) ? 1.f : -1.f;
        float vx = (corner & 1) ? 1.f : -1.f;
        float yc = cy + vy * (1.f/(float)HH) + EPSF;
        float xc = cx + vx * (1.f/(float)WW) + EPSF;
        yc = fminf(fmaxf(yc, -1.f + EPSF), 1.f - EPSF);
        xc = fminf(fmaxf(xc, -1.f + EPSF), 1.f - EPSF);
        int iy = (int)rintf((yc + 1.f) * ((float)HH * 0.5f) - 0.5f);
        int ix = (int)rintf((xc + 1.f) * ((float)WW * 0.5f) - 0.5f);
        iy = min(max(iy, 0), HH - 1);
        ix = min(max(ix, 0), WW - 1);
        float sy = (((float)iy + 0.5f) / (float)HH) * 2.f - 1.f;
        float sx = (((float)ix + 0.5f) / (float)WW) * 2.f - 1.f;
        float ry = (cy - sy) * (float)HH;
        float rx = (cx - sx) * (float)WW;
        float* sA = qs + QS_A + nb*SABUF;
        sA[row*ASTR +  96] = ry;
        sA[row*ASTR +  97] = rx;
        sA[row*ASTR +  98] = cy;
        sA[row*ASTR +  99] = cx;
        sA[row*ASTR + 100] = ce.x * (float)HH;
        sA[row*ASTR + 101] = ce.y * (float)WW;
        sA[row*ASTR + 102] = 0.f;
        sA[row*ASTR + 103] = 0.f;
        sAreaB[nb*QROWS + row] = fabsf(ry * rx) + EPSF;
        return ((b*HH + iy)*WW + ix) * 96;
    };
    auto do_gather = [&](int offR, int nb) {
        int off = __shfl_sync(0xffffffff, offR, lane >> 1);
        int row = stripe + (lane >> 1);
        int half = lane & 1;
        const float* src = g_aspp + off + half*48;
        float* dst = qs + QS_A + nb*SABUF + row*ASTR + half*48;
        #pragma unroll
        for (int i = 0; i < 12; i++)
            cpasync16(smem_u32(dst + i*4), src + i*4);
        cpcommit();
    };
    auto load_cc = [&](int T, float2& co, float2& ce) {
        if (lane < 16) {
            int q = T*48 + w*4 + (lane >> 2);
            co = *(const float2*)&coords[q*2];
            ce = *(const float2*)&cells[q*2];
        }
    };

    int t0 = blockIdx.x;
    if (t0 >= NT) return;
    float2 cc0, ce0;
    load_cc(t0, cc0, ce0);
    int offR = 0;
    if (lane < 16) offR = do_meta(t0, 0, cc0, ce0);
    do_gather(offR, 0);
    load_cc(min(t0 + GS, NT - 1), cc0, ce0);

    int bufsel = 0;
    #pragma unroll 1
    for (int tI = t0; tI < NT; tI += GS) {
        int tn = min(tI + GS, NT - 1);
        int nb = bufsel ^ 1;
        int offN = 0;
        if (lane < 16) offN = do_meta(tn, nb, cc0, ce0);
        do_gather(offN, nb);
        load_cc(min(tI + 2*GS, NT - 1), cc0, ce0);

        asm volatile("cp.async.wait_group 1;\n");
        __syncwarp();

        float* sA = qs + QS_A + bufsel*SABUF;

        // ---- GEMM1 ----
        float acc[8][4];
        #pragma unroll
        for (int n = 0; n < 8; n++)
            #pragma unroll
            for (int r = 0; r < 4; r++) acc[n][r] = 0.f;
        #pragma unroll 1
        for (int ks = 0; ks < 13; ks++) {
            const float* ap = &sA[(stripe + gid)*ASTR + ks*8 + c4];
            unsigned a0 = cvt_tf32(ap[0]);
            unsigned a1 = cvt_tf32(ap[8*ASTR]);
            unsigned a2 = cvt_tf32(ap[4]);
            unsigned a3 = cvt_tf32(ap[8*ASTR + 4]);
            const uint2* wrow = ((const uint2*)sW0f) + (ks*8)*32 + lane;
            #pragma unroll
            for (int n = 0; n < 8; n++) {
                uint2 bb = wrow[n*32];
                mma_tf32(acc[n][0], acc[n][1], acc[n][2], acc[n][3],
                         a0, a1, a2, a3, bb.x, bb.y);
            }
        }
        __syncwarp();
        #pragma unroll
        for (int n = 0; n < 8; n++) {
            int col = n*8 + 2*c4;
            int r0 = stripe + gid;
            sA[r0*ASTR + col]       = fmaxf(acc[n][0] + sB0[col],     0.f);
            sA[r0*ASTR + col + 1]   = fmaxf(acc[n][1] + sB0[col + 1], 0.f);
            sA[(r0+8)*ASTR + col]   = fmaxf(acc[n][2] + sB0[col],     0.f);
            sA[(r0+8)*ASTR + col+1] = fmaxf(acc[n][3] + sB0[col + 1], 0.f);
        }
        __syncwarp();

        // ---- GEMM2 ----
        #pragma unroll
        for (int n = 0; n < 8; n++)
            #pragma unroll
            for (int r = 0; r < 4; r++) acc[n][r] = 0.f;
        #pragma unroll 1
        for (int ks = 0; ks < 8; ks++) {
            const float* ap = &sA[(stripe + gid)*ASTR + ks*8 + c4];
            unsigned a0 = cvt_tf32(ap[0]);
            unsigned a1 = cvt_tf32(ap[8*ASTR]);
            unsigned a2 = cvt_tf32(ap[4]);
            unsigned a3 = cvt_tf32(ap[8*ASTR + 4]);
            const uint2* wrow = ((const uint2*)sW1f) + (ks*8)*32 + lane;
            #pragma unroll
            for (int n = 0; n < 8; n++) {
                uint2 bb = wrow[n*32];
                mma_tf32(acc[n][0], acc[n][1], acc[n][2], acc[n][3],
                         a0, a1, a2, a3, bb.x, bb.y);
            }
        }
        // ---- fused GEMM3 ----
        {
            float p0 = 0.f, p1 = 0.f;
            #pragma unroll
            for (int n = 0; n < 8; n++) {
                int col = n*8 + 2*c4;
                float h00 = fmaxf(acc[n][0] + sB1[col],     0.f);
                float h01 = fmaxf(acc[n][1] + sB1[col + 1], 0.f);
                float h10 = fmaxf(acc[n][2] + sB1[col],     0.f);
                float h11 = fmaxf(acc[n][3] + sB1[col + 1], 0.f);
                p0 = fmaf(h00, w2r[n][0], fmaf(h01, w2r[n][1], p0));
                p1 = fmaf(h10, w2r[n][0], fmaf(h11, w2r[n][1], p1));
            }
            p0 += __shfl_xor_sync(0xffffffff, p0, 1);
            p0 += __shfl_xor_sync(0xffffffff, p0, 2);
            p1 += __shfl_xor_sync(0xffffffff, p1, 1);
            p1 += __shfl_xor_sync(0xffffffff, p1, 2);
            if (c4 == 0) {
                sPredW[stripe + gid]     = p0 + b2v;
                sPredW[stripe + gid + 8] = p1 + b2v;
            }
        }
        __syncwarp();
        if (lane < 4) {
            float num = 0.f, den = 0.f;
            #pragma unroll
            for (int c = 0; c < 4; c++) {
                float ar = sAreaB[bufsel*QROWS + stripe + lane*4 + (3 - c)];
                num = fmaf(sPredW[stripe + lane*4 + c], ar, num);
                den += ar;
            }
            out[tI*48 + w*4 + lane] = num / den;
        }
        __syncwarp();
        bufsel ^= 1;
    }
    asm volatile("cp.async.wait_group 0;\n");
}

// ---------------- launch ----------------
extern "C" void kernel_launch(void* const* d_in, const int* in_sizes, int n_in,
                              void* d_out, int out_size) {
    const float* feats2  = (const float*)d_in[0];
    const float* feats4  = (const float*)d_in[1];
    const float* feats32 = (const float*)d_in[2];
    const float* coords  = (const float*)d_in[3];
    const float* cells   = (const float*)d_in[4];
    const float* w2  = (const float*)d_in[5];
    const float* b2  = (const float*)d_in[6];
    const float* w4  = (const float*)d_in[7];
    const float* b4  = (const float*)d_in[8];
    const float* w32 = (const float*)d_in[9];
    const float* b32 = (const float*)d_in[10];
    const float* wf  = (const float*)d_in[11];
    const float* bf  = (const float*)d_in[12];
    const float* mw0 = (const float*)d_in[13];
    const float* mb0 = (const float*)d_in[14];
    const float* mw1 = (const float*)d_in[15];
    const float* mb1 = (const float*)d_in[16];
    const float* mw2 = (const float*)d_in[17];
    const float* mb2 = (const float*)d_in[18];
    float* out = (float*)d_out;

    float *pX, *pA4, *pA32;
    cudaGetSymbolAddress((void**)&pX,  g_X);
    cudaGetSymbolAddress((void**)&pA4, g_a4);
    cudaGetSymbolAddress((void**)&pA32, g_a32);

    cudaFuncSetAttribute(conv3x3_k, cudaFuncAttributeMaxDynamicSharedMemorySize, CONV_SMEM * 4);
    cudaFuncSetAttribute(query_k,  cudaFuncAttributeMaxDynamicSharedMemorySize, QS_TOTAL * 4);

    conv1x1_feats2_k<<<NP/32, 256>>>(feats2, w2, b2, pX);
    conv1x1_planar_k<<<(BB*96*96)/32, 256>>>(feats4, w4, b4, pA4, BB*96*96, 96);
    conv1x1_planar_k<<<(BB*24*24)/32, 256>>>(feats32, w32, b32, pA32, BB*24*24, 160);
    {
        int total = 64*BB*HH*WW;
        upsample_k<<<(total + 255)/256, 256>>>();
    }
    {
        dim3 grid(WW/16, HH/16, BB);
        conv3x3_k<<<grid, 384, CONV_SMEM * 4>>>(wf, bf);
    }
    query_k<<<148, 384, QS_TOTAL * 4>>>(coords, cells, mw0, mb0, mw1, mb1, mw2, mb2, out);
}